// round 13
// baseline (speedup 1.0000x reference)
#include <cuda_runtime.h>
#include <cuda_bf16.h>
#include <cstdint>

// BilateralFilter (SqueezeSeg): out[b,z,a,k,c] = exp(-||x[b,z,a]-nbr_k||^2 / (2*theta_c^2))
// B=16, Z=64, A=512, K=14 (3x5 minus center), theta=[.015,.015,.01,.01]
// -> per (pixel,k) output float4 = (e1,e1,e2,e2), only 2 distinct exps.
//
// R13: NO shared memory, NO barriers. Input is 6.3 MB (L2-resident, warm
// across replays); center + neighbor float3 read directly via LDG with
// predicated zero-padding. Warps are fully independent -> all latency hidden
// by occupancy. Keeps: coalesced tid->(p,k) store mapping, loop-invariant
// k-decode, 4 outputs/thread/z-row, ZC=4 z-loop, __stcs, __expf.

#define BB 16
#define ZZ 64
#define AA 512
#define KK 14

#define TA 256                // pixels (a) per CTA
#define NT 896                // threads
#define PT 4                  // outputs per thread per z-row
#define ZC 4                  // z-rows per CTA

__global__ __launch_bounds__(NT, 2)
void bilateral_kernel(const float* __restrict__ x, float4* __restrict__ out)
{
    const int tid = threadIdx.x;
    const int a0 = blockIdx.x * TA;
    const int z0 = blockIdx.y * ZC;
    const int b  = blockIdx.z;

    // ---- decode once: k, (i,j) invariant for this thread ----
    const int p0 = tid / KK;          // 0..63
    const int k  = tid - p0 * KK;     // 0..13
    const int kk = k + (k >= 7);      // skip center (flat 7)
    const int i  = kk / 5;            // 0..2
    const int j  = kk - i * 5;        // 0..4
    const int dj = j - 2;             // -2..2

    const float C1 = -1.0f / (2.0f * 0.015f * 0.015f);
    const float C2 = -1.0f / (2.0f * 0.01f  * 0.01f );

    const float* xb = x + (size_t)b * ZZ * AA * 3;
    float4* ob = out + ((size_t)((b * ZZ + z0) * AA + a0)) * KK + tid;

    #pragma unroll 1
    for (int z = z0; z < z0 + ZC; ++z) {
        const float* rowC = xb + (size_t)z * AA * 3;
        const int zr = z - 1 + i;
        const bool zok = (zr >= 0) && (zr < ZZ);
        const float* rowN = xb + (size_t)zr * AA * 3;

        #pragma unroll
        for (int it = 0; it < PT; ++it) {
            const int a = a0 + p0 + it * 64;
            const float cx = rowC[a * 3 + 0];
            const float cy = rowC[a * 3 + 1];
            const float cz = rowC[a * 3 + 2];

            const int an = a + dj;
            const bool ok = zok && (an >= 0) && (an < AA);
            const float nx = ok ? rowN[an * 3 + 0] : 0.f;
            const float ny = ok ? rowN[an * 3 + 1] : 0.f;
            const float nz = ok ? rowN[an * 3 + 2] : 0.f;

            const float dx = cx - nx;
            const float dy = cy - ny;
            const float dz = cz - nz;
            const float d2 = fmaf(dz, dz, fmaf(dy, dy, dx * dx));
            const float e1 = __expf(d2 * C1);
            const float e2 = __expf(d2 * C2);
            __stcs(&ob[it * NT], make_float4(e1, e1, e2, e2));
        }

        ob += (size_t)AA * KK;
    }
}

extern "C" void kernel_launch(void* const* d_in, const int* in_sizes, int n_in,
                              void* d_out, int out_size)
{
    (void)in_sizes; (void)n_in; (void)out_size;
    const float* x = (const float*)d_in[0];
    float4* out = (float4*)d_out;

    dim3 grid(AA / TA, ZZ / ZC, BB);   // 2 x 16 x 16 = 512 CTAs
    dim3 block(NT);                    // 896 threads
    bilateral_kernel<<<grid, block>>>(x, out);
}